// round 7
// baseline (speedup 1.0000x reference)
#include <cuda_runtime.h>
#include <cuda_bf16.h>
#include <cstdint>
#include <math.h>

#define HID 128
#define MAXN 50000
#define MAXE 800000

typedef unsigned long long ull;

// ---------------- scratch (device globals; zero-initialized at load) ----------------
__device__ int   g_counts[MAXN + 1];   // scan_kernel re-zeroes after use each call
__device__ int   g_off[MAXN + 1];
__device__ int   g_cursor[MAXN];
__device__ int   g_esrc[MAXE];
__device__ float g_aggr[(size_t)MAXN * HID];
__device__ float g_h1[(size_t)MAXN * HID];
__device__ float g_h2[(size_t)MAXN * HID];

// ---------------- f32x2 packed-math macros ----------------
#define PACKF2(out, lo, hi) \
    asm("mov.b64 %0, {%1, %2};" : "=l"(out) : "f"(lo), "f"(hi))
#define UNPACKF2(lo, hi, v) \
    asm("mov.b64 {%0, %1}, %2;" : "=f"(lo), "=f"(hi) : "l"(v))
#define FMAF2(acc, a, b) \
    asm("fma.rn.f32x2 %0, %1, %2, %0;" : "+l"(acc) : "l"(a), "l"(b))

// ---------------- CSR build ----------------
__global__ void hist_kernel(const int* __restrict__ dst, int* __restrict__ counts, int E) {
    int e = blockIdx.x * blockDim.x + threadIdx.x;
    if (e < E) atomicAdd(&counts[dst[e]], 1);
}

// single-block scan: counts -> off/cursor, then re-zero counts for next call
__global__ void scan_kernel(int* __restrict__ counts, int* __restrict__ off,
                            int* __restrict__ cursor, int n) {
    __shared__ int part[1024];
    int tid = threadIdx.x;
    int chunk = (n + 1023) >> 10;
    int start = tid * chunk;
    int end = start + chunk; if (end > n) end = n;
    int s = 0;
    #pragma unroll 4
    for (int i = start; i < end; i++) s += counts[i];
    part[tid] = s;
    __syncthreads();
    for (int d = 1; d < 1024; d <<= 1) {
        int v = (tid >= d) ? part[tid - d] : 0;
        __syncthreads();
        part[tid] += v;
        __syncthreads();
    }
    int pre = (tid == 0) ? 0 : part[tid - 1];
    for (int i = start; i < end; i++) {
        int c = counts[i];
        counts[i] = 0;          // leave zeroed for next call's hist
        off[i] = pre;
        cursor[i] = pre;
        pre += c;
    }
    if (end == n) off[n] = pre;
}

__global__ void fill_kernel(const int* __restrict__ src, const int* __restrict__ dst,
                            int* __restrict__ cursor, int* __restrict__ esrc, int E) {
    int e = blockIdx.x * blockDim.x + threadIdx.x;
    if (e < E) {
        int d = dst[e];
        int pos = atomicAdd(&cursor[d], 1);
        esrc[pos] = src[e];
    }
}

// ---------------- gather-aggregate (mean): warp per dst node, MLP=4 ----------------
__global__ void gather_kernel(const float* __restrict__ feat, const int* __restrict__ esrc,
                              const int* __restrict__ off, float* __restrict__ aggr, int n) {
    int w = (blockIdx.x * blockDim.x + threadIdx.x) >> 5;
    int lane = threadIdx.x & 31;
    if (w >= n) return;
    int o0 = off[w], o1 = off[w + 1];
    const float4* f4 = (const float4*)feat;
    float4 a0 = {0.f, 0.f, 0.f, 0.f};
    float4 a1 = {0.f, 0.f, 0.f, 0.f};
    int k = o0;
    for (; k + 4 <= o1; k += 4) {
        int s0 = __ldg(esrc + k);
        int s1 = __ldg(esrc + k + 1);
        int s2 = __ldg(esrc + k + 2);
        int s3 = __ldg(esrc + k + 3);
        float4 v0 = f4[(size_t)s0 * 32 + lane];
        float4 v1 = f4[(size_t)s1 * 32 + lane];
        float4 v2 = f4[(size_t)s2 * 32 + lane];
        float4 v3 = f4[(size_t)s3 * 32 + lane];
        a0.x += v0.x; a0.y += v0.y; a0.z += v0.z; a0.w += v0.w;
        a1.x += v1.x; a1.y += v1.y; a1.z += v1.z; a1.w += v1.w;
        a0.x += v2.x; a0.y += v2.y; a0.z += v2.z; a0.w += v2.w;
        a1.x += v3.x; a1.y += v3.y; a1.z += v3.z; a1.w += v3.w;
    }
    for (; k < o1; k++) {
        int s = __ldg(esrc + k);
        float4 v = f4[(size_t)s * 32 + lane];
        a0.x += v.x; a0.y += v.y; a0.z += v.z; a0.w += v.w;
    }
    float inv = 1.0f / fmaxf((float)(o1 - o0), 1.0f);
    float4 r;
    r.x = (a0.x + a1.x) * inv;
    r.y = (a0.y + a1.y) * inv;
    r.z = (a0.z + a1.z) * inv;
    r.w = (a0.w + a1.w) * inv;
    ((float4*)aggr)[(size_t)w * 32 + lane] = r;
}

// ---------------- register-blocked f32x2 SAGE layer (+ optional fused logits) ----------------
// out[node][col] = relu( sum_k S[node][k]*W[k][col] + b[col] ), S=[A|X], W=[Wl;Wr], K=256.
// 256 threads: c = tid&15 (cols [8c,8c+8)), ng = tid>>4 (nodes [8ng,8ng+8)).
// Thread tile 8 nodes x 8 cols = 32 FFMA2/k from 12 LDS64/k -> fma-pipe-bound.
// If doLogits: also computes logits = h @ Wout + bout via width-16 shfl reduction.
#define KCH 64
#define SROW 129
#define SM_BIAS 0
#define SM_WOUT 512
#define SM_W 2048
#define SM_S (2048 + 256 * 64 * 8)
#define LAYER_SMEM (SM_S + KCH * SROW * 8)

__global__ void __launch_bounds__(256, 1)
layer_kernel(const float* __restrict__ A, const float* __restrict__ X,
             const float* __restrict__ Wl, const float* __restrict__ Wr,
             const float* __restrict__ bias, float* __restrict__ out, int n,
             const float* __restrict__ Wout, const float* __restrict__ bout,
             float* __restrict__ logits, int doLogits) {
    extern __shared__ char smem[];
    float* sBias = (float*)(smem + SM_BIAS);
    float* sWout = (float*)(smem + SM_WOUT);  // [128][2]
    ull* sW = (ull*)(smem + SM_W);            // [256][64]
    ull* sS = (ull*)(smem + SM_S);            // [KCH][SROW]

    int tid = threadIdx.x;
    int c  = tid & 15;
    int ng = tid >> 4;

    // stage W (transposed pair layout) + bias (+ Wout), once per block
    for (int idx = tid; idx < 256 * 64; idx += 256) {
        int k = idx >> 6, p = idx & 63;
        int cc = p >> 2, j = p & 3;
        const float* wsrc = (k < 128) ? (Wl + (size_t)k * 128) : (Wr + (size_t)(k - 128) * 128);
        float w0 = wsrc[2 * p];
        float w1 = wsrc[2 * p + 1];
        ull wp;
        PACKF2(wp, w0, w1);
        sW[k * 64 + j * 16 + cc] = wp;
    }
    if (tid < 128) sBias[tid] = bias[tid];
    if (doLogits && tid < 256) sWout[tid] = Wout[tid];
    float bo0 = 0.f, bo1 = 0.f;
    if (doLogits) { bo0 = __ldg(bout); bo1 = __ldg(bout + 1); }

    int nTiles = (n + 127) >> 7;
    for (int tile = blockIdx.x; tile < nTiles; tile += gridDim.x) {
        ull acc[8][4];
        #pragma unroll
        for (int i = 0; i < 8; i++)
            #pragma unroll
            for (int j = 0; j < 4; j++) acc[i][j] = 0ull;

        #pragma unroll
        for (int kc = 0; kc < 4; kc++) {
            __syncthreads();   // protects sS reuse (and sW/bias on first pass)
            {
                int q = tid & 15;          // float4 index within 64-k chunk
                int nl0 = tid >> 4;        // 0..15
                const float* base = (kc < 2) ? A : X;
                int kbase = (kc & 1) * 64;
                #pragma unroll
                for (int pass = 0; pass < 8; pass++) {
                    int nodeLoc = pass * 16 + nl0;
                    int node = tile * 128 + nodeLoc;
                    float4 v;
                    if (node < n) v = *(const float4*)(base + (size_t)node * HID + kbase + q * 4);
                    else v = make_float4(0.f, 0.f, 0.f, 0.f);
                    ull d0, d1, d2, d3;
                    PACKF2(d0, v.x, v.x);
                    PACKF2(d1, v.y, v.y);
                    PACKF2(d2, v.z, v.z);
                    PACKF2(d3, v.w, v.w);
                    int kl = q * 4;
                    sS[(kl + 0) * SROW + nodeLoc] = d0;
                    sS[(kl + 1) * SROW + nodeLoc] = d1;
                    sS[(kl + 2) * SROW + nodeLoc] = d2;
                    sS[(kl + 3) * SROW + nodeLoc] = d3;
                }
            }
            __syncthreads();

            const ull* wbase = sW + (size_t)kc * 64 * 64 + c;
            #pragma unroll 2
            for (int k = 0; k < KCH; k++) {
                const ull* srow = sS + k * SROW + ng * 8;
                const ull* wrow = wbase + k * 64;
                ull a0 = srow[0], a1 = srow[1], a2 = srow[2], a3 = srow[3];
                ull a4 = srow[4], a5 = srow[5], a6 = srow[6], a7 = srow[7];
                ull w0 = wrow[0], w1 = wrow[16], w2 = wrow[32], w3 = wrow[48];
                FMAF2(acc[0][0], a0, w0); FMAF2(acc[0][1], a0, w1);
                FMAF2(acc[0][2], a0, w2); FMAF2(acc[0][3], a0, w3);
                FMAF2(acc[1][0], a1, w0); FMAF2(acc[1][1], a1, w1);
                FMAF2(acc[1][2], a1, w2); FMAF2(acc[1][3], a1, w3);
                FMAF2(acc[2][0], a2, w0); FMAF2(acc[2][1], a2, w1);
                FMAF2(acc[2][2], a2, w2); FMAF2(acc[2][3], a2, w3);
                FMAF2(acc[3][0], a3, w0); FMAF2(acc[3][1], a3, w1);
                FMAF2(acc[3][2], a3, w2); FMAF2(acc[3][3], a3, w3);
                FMAF2(acc[4][0], a4, w0); FMAF2(acc[4][1], a4, w1);
                FMAF2(acc[4][2], a4, w2); FMAF2(acc[4][3], a4, w3);
                FMAF2(acc[5][0], a5, w0); FMAF2(acc[5][1], a5, w1);
                FMAF2(acc[5][2], a5, w2); FMAF2(acc[5][3], a5, w3);
                FMAF2(acc[6][0], a6, w0); FMAF2(acc[6][1], a6, w1);
                FMAF2(acc[6][2], a6, w2); FMAF2(acc[6][3], a6, w3);
                FMAF2(acc[7][0], a7, w0); FMAF2(acc[7][1], a7, w1);
                FMAF2(acc[7][2], a7, w2); FMAF2(acc[7][3], a7, w3);
            }
        }

        // epilogue: bias + relu + store h; optional fused logits.
        // col pair j holds cols (8c+2j, 8c+2j+1). No early break: shfl needs all lanes.
        #pragma unroll
        for (int i = 0; i < 8; i++) {
            int node = tile * 128 + ng * 8 + i;
            float h[8];
            #pragma unroll
            for (int j = 0; j < 4; j++) {
                float v0, v1;
                UNPACKF2(v0, v1, acc[i][j]);
                h[2 * j + 0] = fmaxf(v0 + sBias[c * 8 + 2 * j + 0], 0.f);
                h[2 * j + 1] = fmaxf(v1 + sBias[c * 8 + 2 * j + 1], 0.f);
            }
            if (node < n) {
                float* po = out + (size_t)node * HID + c * 8;
                float4 o;
                o.x = h[0]; o.y = h[1]; o.z = h[2]; o.w = h[3];
                *(float4*)po = o;
                o.x = h[4]; o.y = h[5]; o.z = h[6]; o.w = h[7];
                *(float4*)(po + 4) = o;
            }
            if (doLogits) {
                float pl0 = 0.f, pl1 = 0.f;
                #pragma unroll
                for (int j = 0; j < 8; j++) {
                    float wv0 = sWout[(c * 8 + j) * 2 + 0];
                    float wv1 = sWout[(c * 8 + j) * 2 + 1];
                    pl0 = fmaf(h[j], wv0, pl0);
                    pl1 = fmaf(h[j], wv1, pl1);
                }
                #pragma unroll
                for (int off = 8; off > 0; off >>= 1) {
                    pl0 += __shfl_down_sync(0xFFFFFFFFu, pl0, off, 16);
                    pl1 += __shfl_down_sync(0xFFFFFFFFu, pl1, off, 16);
                }
                if (c == 0 && node < n) {
                    logits[(size_t)node * 2 + 0] = pl0 + bo0;
                    logits[(size_t)node * 2 + 1] = pl1 + bo1;
                }
            }
        }
    }
}

// ---------------- launch ----------------
extern "C" void kernel_launch(void* const* d_in, const int* in_sizes, int n_in,
                              void* d_out, int out_size) {
    const float* x    = (const float*)d_in[0];
    const int*   ei   = (const int*)d_in[1];   // int32 on device
    const float* W1l  = (const float*)d_in[2];
    const float* W1r  = (const float*)d_in[3];
    const float* b1   = (const float*)d_in[4];
    const float* W2l  = (const float*)d_in[5];
    const float* W2r  = (const float*)d_in[6];
    const float* b2   = (const float*)d_in[7];
    const float* Wout = (const float*)d_in[8];
    const float* bout = (const float*)d_in[9];
    float* dout = (float*)d_out;

    int n = in_sizes[0] / HID;
    int E = in_sizes[1] / 2;
    const int* src = ei;
    const int* dst = ei + E;

    int *p_counts, *p_off, *p_cursor, *p_esrc;
    float *p_aggr, *p_h1, *p_h2;
    cudaGetSymbolAddress((void**)&p_counts, g_counts);
    cudaGetSymbolAddress((void**)&p_off,    g_off);
    cudaGetSymbolAddress((void**)&p_cursor, g_cursor);
    cudaGetSymbolAddress((void**)&p_esrc,   g_esrc);
    cudaGetSymbolAddress((void**)&p_aggr,   g_aggr);
    cudaGetSymbolAddress((void**)&p_h1,     g_h1);
    cudaGetSymbolAddress((void**)&p_h2,     g_h2);

    cudaFuncSetAttribute(layer_kernel, cudaFuncAttributeMaxDynamicSharedMemorySize, LAYER_SMEM);

    // tuple output: logits [n*2] then h [n*128]
    float* hOut = ((size_t)out_size >= (size_t)n * (HID + 2)) ? (dout + (size_t)n * 2) : p_h2;

    // ---- CSR build (counts[] are zero on entry; scan re-zeroes them) ----
    hist_kernel<<<(E + 255) / 256, 256>>>(dst, p_counts, E);
    scan_kernel<<<1, 1024>>>(p_counts, p_off, p_cursor, n);
    fill_kernel<<<(E + 255) / 256, 256>>>(src, dst, p_cursor, p_esrc, E);

    int gatherGrid = (n * 32 + 255) / 256;
    int nTiles = (n + 127) >> 7;
    int layerGrid = nTiles < 148 ? nTiles : 148;

    // ---- layer 1 ----
    gather_kernel<<<gatherGrid, 256>>>(x, p_esrc, p_off, p_aggr, n);
    layer_kernel<<<layerGrid, 256, LAYER_SMEM>>>(p_aggr, x, W1l, W1r, b1, p_h1, n,
                                                 Wout, bout, dout, 0);

    // ---- layer 2 (+ fused logits head) ----
    gather_kernel<<<gatherGrid, 256>>>(p_h1, p_esrc, p_off, p_aggr, n);
    layer_kernel<<<layerGrid, 256, LAYER_SMEM>>>(p_aggr, p_h1, W2l, W2r, b2, hOut, n,
                                                 Wout, bout, dout, 1);
}

// round 9
// speedup vs baseline: 1.3191x; 1.3191x over previous
#include <cuda_runtime.h>
#include <cuda_bf16.h>
#include <cstdint>
#include <math.h>

#define HID 128
#define MAXN 50000
#define MAXE 800000

typedef unsigned long long ull;

// ---------------- scratch (device globals; zero-initialized at load) ----------------
__device__ int   g_counts[MAXN + 1];   // scan_kernel re-zeroes after use each call
__device__ int   g_off[MAXN + 1];
__device__ int   g_cursor[MAXN];
__device__ int   g_esrc[MAXE];
__device__ float g_aggr[(size_t)MAXN * HID];
__device__ float g_h1[(size_t)MAXN * HID];
__device__ float g_h2[(size_t)MAXN * HID];

// low = a, high = b
#define CVT_BF16X2_F32(result, a, b) \
    asm("cvt.rn.satfinite.bf16x2.f32 %0, %1, %2;" : "=r"(result) : "f"(b), "f"(a))

#define MMA_BF16(c, a0, a1, a2, a3, b0, b1) \
    asm volatile("mma.sync.aligned.m16n8k16.row.col.f32.bf16.bf16.f32 " \
        "{%0,%1,%2,%3}, {%4,%5,%6,%7}, {%8,%9}, {%0,%1,%2,%3};" \
        : "+f"((c)[0]), "+f"((c)[1]), "+f"((c)[2]), "+f"((c)[3]) \
        : "r"(a0), "r"(a1), "r"(a2), "r"(a3), "r"(b0), "r"(b1))

// ---------------- CSR build ----------------
__global__ void hist_kernel(const int* __restrict__ dst, int* __restrict__ counts, int E) {
    int e = blockIdx.x * blockDim.x + threadIdx.x;
    if (e < E) atomicAdd(&counts[dst[e]], 1);
}

__global__ void scan_kernel(int* __restrict__ counts, int* __restrict__ off,
                            int* __restrict__ cursor, int n) {
    __shared__ int part[1024];
    int tid = threadIdx.x;
    int chunk = (n + 1023) >> 10;
    int start = tid * chunk;
    int end = start + chunk; if (end > n) end = n;
    int s = 0;
    #pragma unroll 4
    for (int i = start; i < end; i++) s += counts[i];
    part[tid] = s;
    __syncthreads();
    for (int d = 1; d < 1024; d <<= 1) {
        int v = (tid >= d) ? part[tid - d] : 0;
        __syncthreads();
        part[tid] += v;
        __syncthreads();
    }
    int pre = (tid == 0) ? 0 : part[tid - 1];
    for (int i = start; i < end; i++) {
        int c = counts[i];
        counts[i] = 0;          // leave zeroed for next call's hist
        off[i] = pre;
        cursor[i] = pre;
        pre += c;
    }
    if (end == n) off[n] = pre;
}

__global__ void fill_kernel(const int* __restrict__ src, const int* __restrict__ dst,
                            int* __restrict__ cursor, int* __restrict__ esrc, int E) {
    int e = blockIdx.x * blockDim.x + threadIdx.x;
    if (e < E) {
        int d = dst[e];
        int pos = atomicAdd(&cursor[d], 1);
        esrc[pos] = src[e];
    }
}

// ---------------- gather-aggregate (mean): warp per dst node, MLP=4 ----------------
__global__ void gather_kernel(const float* __restrict__ feat, const int* __restrict__ esrc,
                              const int* __restrict__ off, float* __restrict__ aggr, int n) {
    int w = (blockIdx.x * blockDim.x + threadIdx.x) >> 5;
    int lane = threadIdx.x & 31;
    if (w >= n) return;
    int o0 = off[w], o1 = off[w + 1];
    const float4* f4 = (const float4*)feat;
    float4 a0 = {0.f, 0.f, 0.f, 0.f};
    float4 a1 = {0.f, 0.f, 0.f, 0.f};
    int k = o0;
    for (; k + 4 <= o1; k += 4) {
        int s0 = __ldg(esrc + k);
        int s1 = __ldg(esrc + k + 1);
        int s2 = __ldg(esrc + k + 2);
        int s3 = __ldg(esrc + k + 3);
        float4 v0 = f4[(size_t)s0 * 32 + lane];
        float4 v1 = f4[(size_t)s1 * 32 + lane];
        float4 v2 = f4[(size_t)s2 * 32 + lane];
        float4 v3 = f4[(size_t)s3 * 32 + lane];
        a0.x += v0.x; a0.y += v0.y; a0.z += v0.z; a0.w += v0.w;
        a1.x += v1.x; a1.y += v1.y; a1.z += v1.z; a1.w += v1.w;
        a0.x += v2.x; a0.y += v2.y; a0.z += v2.z; a0.w += v2.w;
        a1.x += v3.x; a1.y += v3.y; a1.z += v3.z; a1.w += v3.w;
    }
    for (; k < o1; k++) {
        int s = __ldg(esrc + k);
        float4 v = f4[(size_t)s * 32 + lane];
        a0.x += v.x; a0.y += v.y; a0.z += v.z; a0.w += v.w;
    }
    float inv = 1.0f / fmaxf((float)(o1 - o0), 1.0f);
    float4 r;
    r.x = (a0.x + a1.x) * inv;
    r.y = (a0.y + a1.y) * inv;
    r.z = (a0.z + a1.z) * inv;
    r.w = (a0.w + a1.w) * inv;
    ((float4*)aggr)[(size_t)w * 32 + lane] = r;
}

// ---------------- HMMA (mma.sync bf16-split) SAGE layer ----------------
// out[i][j] = relu( b[j] + sum_{k<256} S[i][k] W[k][j] ), S=[A|X], W=[Wl;Wr].
// fp32 -> bf16 hi/lo split; D = Shi Whi + Slo Whi + Shi Wlo in f32 accum.
// smem (word-indexed, k-pair-major):
//   sW32{hi,lo}[col][p], p=k/2 in 0..127, row stride 132 words
//   sS32{hi,lo}[node][p], p in 0..63 per 128-k chunk, row stride 68 words
// Fragments (m16n8k16.row.col, g=lane>>2, t=lane&3, p0=kstep*8, chunk base kc*64):
//   a0=sS[m0+g][p0+t] a1=sS[m0+g+8][p0+t] a2=sS[m0+g][p0+t+4] a3=sS[m0+g+8][p0+t+4]
//   b0=sW[n0+g][kc*64+p0+t] b1=sW[n0+g][kc*64+p0+t+4]
// Warp w owns cols [16w,16w+16) (2 n-tiles), loops 8 m-tiles; acc = 8*2*4 = 64 f32.
#define WSTRIDE 132
#define SSTRIDE 68
#define SM_BIAS 0
#define SM_WHI  512
#define SM_WLO  (512 + 128 * WSTRIDE * 4)
#define SM_SHI  (512 + 2 * 128 * WSTRIDE * 4)
#define SM_SLO  (SM_SHI + 128 * SSTRIDE * 4)
#define LAYER_SMEM (SM_SLO + 128 * SSTRIDE * 4)

__global__ void __launch_bounds__(256, 1)
layer_kernel(const float* __restrict__ A, const float* __restrict__ X,
             const float* __restrict__ Wl, const float* __restrict__ Wr,
             const float* __restrict__ bias, float* __restrict__ out, int n) {
    extern __shared__ char smem[];
    float* sBias = (float*)(smem + SM_BIAS);
    uint32_t* sWhi = (uint32_t*)(smem + SM_WHI);
    uint32_t* sWlo = (uint32_t*)(smem + SM_WLO);
    uint32_t* sShi = (uint32_t*)(smem + SM_SHI);
    uint32_t* sSlo = (uint32_t*)(smem + SM_SLO);

    int tid = threadIdx.x;
    int wid = tid >> 5;
    int lane = tid & 31;
    int g = lane >> 2;
    int t = lane & 3;
    int n0 = wid * 16;

    // ---- stage W hi/lo (once per block): coalesced read, 16-bit scattered STS ----
    {
        uint16_t* sWhi16 = (uint16_t*)(smem + SM_WHI);
        uint16_t* sWlo16 = (uint16_t*)(smem + SM_WLO);
        for (int idx = tid; idx < 256 * 128; idx += 256) {
            int k = idx >> 7;          // 0..255
            int col = idx & 127;
            float w = (k < 128) ? Wl[(size_t)k * 128 + col]
                                : Wr[(size_t)(k - 128) * 128 + col];
            __nv_bfloat16 h = __float2bfloat16(w);
            float rem = w - __bfloat162float(h);
            __nv_bfloat16 l = __float2bfloat16(rem);
            // word stride 132 -> half stride 264
            sWhi16[col * (2 * WSTRIDE) + k] = *(uint16_t*)&h;
            sWlo16[col * (2 * WSTRIDE) + k] = *(uint16_t*)&l;
        }
        if (tid < 128) sBias[tid] = bias[tid];
    }

    int nTiles = (n + 127) >> 7;
    for (int tile = blockIdx.x; tile < nTiles; tile += gridDim.x) {
        float acc[8][2][4];
        #pragma unroll
        for (int m = 0; m < 8; m++)
            #pragma unroll
            for (int nt = 0; nt < 2; nt++)
                #pragma unroll
                for (int q = 0; q < 4; q++) acc[m][nt][q] = 0.f;

        #pragma unroll
        for (int kc = 0; kc < 2; kc++) {
            __syncthreads();   // protects sS reuse (and sW staging on first pass)
            // stage S chunk (128 nodes x 128 k): warp = 1 node row / pass, 16 passes
            {
                int q = tid & 31;          // float4 index 0..31 within row
                int nl0 = tid >> 5;        // 0..7
                const float* base = (kc == 0) ? A : X;
                #pragma unroll
                for (int pass = 0; pass < 16; pass++) {
                    int nodeLoc = pass * 8 + nl0;
                    int node = tile * 128 + nodeLoc;
                    float4 v;
                    if (node < n) v = *(const float4*)(base + (size_t)node * HID + q * 4);
                    else v = make_float4(0.f, 0.f, 0.f, 0.f);
                    uint32_t hp0, hp1;
                    CVT_BF16X2_F32(hp0, v.x, v.y);
                    CVT_BF16X2_F32(hp1, v.z, v.w);
                    __nv_bfloat162 h0 = *(__nv_bfloat162*)&hp0;
                    __nv_bfloat162 h1 = *(__nv_bfloat162*)&hp1;
                    float r0 = v.x - __low2float(h0);
                    float r1 = v.y - __high2float(h0);
                    float r2 = v.z - __low2float(h1);
                    float r3 = v.w - __high2float(h1);
                    uint32_t lp0, lp1;
                    CVT_BF16X2_F32(lp0, r0, r1);
                    CVT_BF16X2_F32(lp1, r2, r3);
                    int wi = nodeLoc * SSTRIDE + 2 * q;   // word index, 8B aligned
                    *(ull*)(sShi + wi) = (ull)hp0 | ((ull)hp1 << 32);
                    *(ull*)(sSlo + wi) = (ull)lp0 | ((ull)lp1 << 32);
                }
            }
            __syncthreads();

            #pragma unroll
            for (int kstep = 0; kstep < 8; kstep++) {
                int p0 = kstep * 8;
                // B fragments for 2 n-tiles, hi+lo  (NOTE: + kc*64 selects the K-chunk)
                uint32_t bhi[2][2], blo[2][2];
                #pragma unroll
                for (int nt = 0; nt < 2; nt++) {
                    int wrow = (n0 + nt * 8 + g) * WSTRIDE + kc * 64 + p0 + t;
                    bhi[nt][0] = sWhi[wrow];
                    bhi[nt][1] = sWhi[wrow + 4];
                    blo[nt][0] = sWlo[wrow];
                    blo[nt][1] = sWlo[wrow + 4];
                }
                #pragma unroll
                for (int m = 0; m < 8; m++) {
                    int r0 = (m * 16 + g) * SSTRIDE + p0 + t;
                    int r1 = r0 + 8 * SSTRIDE;
                    uint32_t ah0 = sShi[r0], ah1 = sShi[r1];
                    uint32_t ah2 = sShi[r0 + 4], ah3 = sShi[r1 + 4];
                    uint32_t al0 = sSlo[r0], al1 = sSlo[r1];
                    uint32_t al2 = sSlo[r0 + 4], al3 = sSlo[r1 + 4];
                    #pragma unroll
                    for (int nt = 0; nt < 2; nt++) {
                        MMA_BF16(acc[m][nt], ah0, ah1, ah2, ah3, bhi[nt][0], bhi[nt][1]);
                        MMA_BF16(acc[m][nt], al0, al1, al2, al3, bhi[nt][0], bhi[nt][1]);
                        MMA_BF16(acc[m][nt], ah0, ah1, ah2, ah3, blo[nt][0], blo[nt][1]);
                    }
                }
            }
        }

        // epilogue: bias + relu + store. Thread (m,nt): rows m*16+g, +8; cols n0+nt*8+2t,+1.
        #pragma unroll
        for (int m = 0; m < 8; m++) {
            #pragma unroll
            for (int nt = 0; nt < 2; nt++) {
                int col = n0 + nt * 8 + 2 * t;
                float b0 = sBias[col], b1 = sBias[col + 1];
                int node0 = tile * 128 + m * 16 + g;
                if (node0 < n) {
                    float2 o;
                    o.x = fmaxf(acc[m][nt][0] + b0, 0.f);
                    o.y = fmaxf(acc[m][nt][1] + b1, 0.f);
                    *(float2*)(out + (size_t)node0 * HID + col) = o;
                }
                int node1 = node0 + 8;
                if (node1 < n) {
                    float2 o;
                    o.x = fmaxf(acc[m][nt][2] + b0, 0.f);
                    o.y = fmaxf(acc[m][nt][3] + b1, 0.f);
                    *(float2*)(out + (size_t)node1 * HID + col) = o;
                }
            }
        }
    }
}

// ---------------- logits head: warp per node ----------------
__global__ void logits_kernel(const float* __restrict__ h, const float* __restrict__ Wout,
                              const float* __restrict__ bout, float* __restrict__ out, int n) {
    int w = (blockIdx.x * blockDim.x + threadIdx.x) >> 5;
    int lane = threadIdx.x & 31;
    if (w >= n) return;
    float4 v = ((const float4*)(h + (size_t)w * HID))[lane];
    int k = lane * 4;
    float s0 = v.x * Wout[(k + 0) * 2 + 0] + v.y * Wout[(k + 1) * 2 + 0] +
               v.z * Wout[(k + 2) * 2 + 0] + v.w * Wout[(k + 3) * 2 + 0];
    float s1 = v.x * Wout[(k + 0) * 2 + 1] + v.y * Wout[(k + 1) * 2 + 1] +
               v.z * Wout[(k + 2) * 2 + 1] + v.w * Wout[(k + 3) * 2 + 1];
    #pragma unroll
    for (int off = 16; off > 0; off >>= 1) {
        s0 += __shfl_xor_sync(0xFFFFFFFFu, s0, off);
        s1 += __shfl_xor_sync(0xFFFFFFFFu, s1, off);
    }
    if (lane == 0) {
        out[(size_t)w * 2 + 0] = s0 + bout[0];
        out[(size_t)w * 2 + 1] = s1 + bout[1];
    }
}

// ---------------- launch ----------------
extern "C" void kernel_launch(void* const* d_in, const int* in_sizes, int n_in,
                              void* d_out, int out_size) {
    const float* x    = (const float*)d_in[0];
    const int*   ei   = (const int*)d_in[1];   // int32 on device
    const float* W1l  = (const float*)d_in[2];
    const float* W1r  = (const float*)d_in[3];
    const float* b1   = (const float*)d_in[4];
    const float* W2l  = (const float*)d_in[5];
    const float* W2r  = (const float*)d_in[6];
    const float* b2   = (const float*)d_in[7];
    const float* Wout = (const float*)d_in[8];
    const float* bout = (const float*)d_in[9];
    float* dout = (float*)d_out;

    int n = in_sizes[0] / HID;
    int E = in_sizes[1] / 2;
    const int* src = ei;
    const int* dst = ei + E;

    int *p_counts, *p_off, *p_cursor, *p_esrc;
    float *p_aggr, *p_h1, *p_h2;
    cudaGetSymbolAddress((void**)&p_counts, g_counts);
    cudaGetSymbolAddress((void**)&p_off,    g_off);
    cudaGetSymbolAddress((void**)&p_cursor, g_cursor);
    cudaGetSymbolAddress((void**)&p_esrc,   g_esrc);
    cudaGetSymbolAddress((void**)&p_aggr,   g_aggr);
    cudaGetSymbolAddress((void**)&p_h1,     g_h1);
    cudaGetSymbolAddress((void**)&p_h2,     g_h2);

    cudaFuncSetAttribute(layer_kernel, cudaFuncAttributeMaxDynamicSharedMemorySize, LAYER_SMEM);

    // tuple output: logits [n*2] then h [n*128]
    float* hOut = ((size_t)out_size >= (size_t)n * (HID + 2)) ? (dout + (size_t)n * 2) : p_h2;

    // ---- CSR build (counts[] zero on entry; scan re-zeroes) ----
    hist_kernel<<<(E + 255) / 256, 256>>>(dst, p_counts, E);
    scan_kernel<<<1, 1024>>>(p_counts, p_off, p_cursor, n);
    fill_kernel<<<(E + 255) / 256, 256>>>(src, dst, p_cursor, p_esrc, E);

    int gatherGrid = (n * 32 + 255) / 256;
    int nTiles = (n + 127) >> 7;
    int layerGrid = nTiles < 148 ? nTiles : 148;

    // ---- layer 1 ----
    gather_kernel<<<gatherGrid, 256>>>(x, p_esrc, p_off, p_aggr, n);
    layer_kernel<<<layerGrid, 256, LAYER_SMEM>>>(p_aggr, x, W1l, W1r, b1, p_h1, n);

    // ---- layer 2 ----
    gather_kernel<<<gatherGrid, 256>>>(p_h1, p_esrc, p_off, p_aggr, n);
    layer_kernel<<<layerGrid, 256, LAYER_SMEM>>>(p_aggr, p_h1, W2l, W2r, b2, hOut, n);

    // ---- head ----
    logits_kernel<<<(n * 32 + 255) / 256, 256>>>(hOut, Wout, bout, dout, n);
}

// round 10
// speedup vs baseline: 1.5191x; 1.1516x over previous
#include <cuda_runtime.h>
#include <cuda_bf16.h>
#include <cuda_fp16.h>
#include <cstdint>
#include <math.h>

#define HID 128
#define MAXN 50000
#define MAXE 800000

typedef unsigned long long ull;

// ---------------- scratch (device globals; zero-initialized at load) ----------------
__device__ int   g_counts[MAXN + 1];   // scan_kernel re-zeroes after use each call
__device__ int   g_off[MAXN + 1];
__device__ int   g_cursor[MAXN];
__device__ int   g_esrc[MAXE];
__device__ float g_aggr[(size_t)MAXN * HID];
__device__ float g_h1[(size_t)MAXN * HID];
__device__ float g_h2[(size_t)MAXN * HID];
// W fp16 hi/lo, pre-laid-out as [col][264 halves] (word stride 132), per layer
__device__ uint4 g_whi[2][4224];   // 2 x 67584 B
__device__ uint4 g_wlo[2][4224];

#define MMA_F16(c, a0, a1, a2, a3, b0, b1) \
    asm volatile("mma.sync.aligned.m16n8k16.row.col.f32.f16.f16.f32 " \
        "{%0,%1,%2,%3}, {%4,%5,%6,%7}, {%8,%9}, {%0,%1,%2,%3};" \
        : "+f"((c)[0]), "+f"((c)[1]), "+f"((c)[2]), "+f"((c)[3]) \
        : "r"(a0), "r"(a1), "r"(a2), "r"(a3), "r"(b0), "r"(b1))

// ---------------- CSR build ----------------
__global__ void hist_kernel(const int* __restrict__ dst, int* __restrict__ counts, int E) {
    int e = blockIdx.x * blockDim.x + threadIdx.x;
    if (e < E) atomicAdd(&counts[dst[e]], 1);
}

__global__ void scan_kernel(int* __restrict__ counts, int* __restrict__ off,
                            int* __restrict__ cursor, int n) {
    __shared__ int part[1024];
    int tid = threadIdx.x;
    int chunk = (n + 1023) >> 10;
    int start = tid * chunk;
    int end = start + chunk; if (end > n) end = n;
    int s = 0;
    #pragma unroll 4
    for (int i = start; i < end; i++) s += counts[i];
    part[tid] = s;
    __syncthreads();
    for (int d = 1; d < 1024; d <<= 1) {
        int v = (tid >= d) ? part[tid - d] : 0;
        __syncthreads();
        part[tid] += v;
        __syncthreads();
    }
    int pre = (tid == 0) ? 0 : part[tid - 1];
    for (int i = start; i < end; i++) {
        int c = counts[i];
        counts[i] = 0;          // leave zeroed for next call's hist
        off[i] = pre;
        cursor[i] = pre;
        pre += c;
    }
    if (end == n) off[n] = pre;
}

__global__ void fill_kernel(const int* __restrict__ src, const int* __restrict__ dst,
                            int* __restrict__ cursor, int* __restrict__ esrc, int E) {
    int e = blockIdx.x * blockDim.x + threadIdx.x;
    if (e < E) {
        int d = dst[e];
        int pos = atomicAdd(&cursor[d], 1);
        esrc[pos] = src[e];
    }
}

// ---------------- W fp16 hi/lo split (once per call, both layers) ----------------
// layout: half index col*264 + k  (word stride 132; matches layer smem layout)
__global__ void wsplit_kernel(const float* __restrict__ W1l, const float* __restrict__ W1r,
                              const float* __restrict__ W2l, const float* __restrict__ W2r) {
    int idx = blockIdx.x * blockDim.x + threadIdx.x;   // 2*256*128 = 65536
    if (idx >= 2 * 256 * 128) return;
    int layer = idx >> 15;
    int r = idx & 32767;
    int k = r >> 7;
    int col = r & 127;
    const float* srcm;
    if (layer == 0) srcm = (k < 128) ? (W1l + (size_t)k * 128) : (W1r + (size_t)(k - 128) * 128);
    else            srcm = (k < 128) ? (W2l + (size_t)k * 128) : (W2r + (size_t)(k - 128) * 128);
    float w = srcm[col];
    __half h = __float2half(w);
    float rem = w - __half2float(h);
    __half l = __float2half(rem);
    ((uint16_t*)g_whi[layer])[col * 264 + k] = *(uint16_t*)&h;
    ((uint16_t*)g_wlo[layer])[col * 264 + k] = *(uint16_t*)&l;
}

// ---------------- gather-aggregate (mean): warp per dst node, MLP=4 ----------------
__global__ void gather_kernel(const float* __restrict__ feat, const int* __restrict__ esrc,
                              const int* __restrict__ off, float* __restrict__ aggr, int n) {
    int w = (blockIdx.x * blockDim.x + threadIdx.x) >> 5;
    int lane = threadIdx.x & 31;
    if (w >= n) return;
    int o0 = off[w], o1 = off[w + 1];
    const float4* f4 = (const float4*)feat;
    float4 a0 = {0.f, 0.f, 0.f, 0.f};
    float4 a1 = {0.f, 0.f, 0.f, 0.f};
    int k = o0;
    for (; k + 4 <= o1; k += 4) {
        int s0 = __ldg(esrc + k);
        int s1 = __ldg(esrc + k + 1);
        int s2 = __ldg(esrc + k + 2);
        int s3 = __ldg(esrc + k + 3);
        float4 v0 = f4[(size_t)s0 * 32 + lane];
        float4 v1 = f4[(size_t)s1 * 32 + lane];
        float4 v2 = f4[(size_t)s2 * 32 + lane];
        float4 v3 = f4[(size_t)s3 * 32 + lane];
        a0.x += v0.x; a0.y += v0.y; a0.z += v0.z; a0.w += v0.w;
        a1.x += v1.x; a1.y += v1.y; a1.z += v1.z; a1.w += v1.w;
        a0.x += v2.x; a0.y += v2.y; a0.z += v2.z; a0.w += v2.w;
        a1.x += v3.x; a1.y += v3.y; a1.z += v3.z; a1.w += v3.w;
    }
    for (; k < o1; k++) {
        int s = __ldg(esrc + k);
        float4 v = f4[(size_t)s * 32 + lane];
        a0.x += v.x; a0.y += v.y; a0.z += v.z; a0.w += v.w;
    }
    float inv = 1.0f / fmaxf((float)(o1 - o0), 1.0f);
    float4 r;
    r.x = (a0.x + a1.x) * inv;
    r.y = (a0.y + a1.y) * inv;
    r.z = (a0.z + a1.z) * inv;
    r.w = (a0.w + a1.w) * inv;
    ((float4*)aggr)[(size_t)w * 32 + lane] = r;
}

// ---------------- HMMA (mma.sync fp16, 2-term) SAGE layer ----------------
// out[i][j] = relu( b[j] + sum_{k<256} S[i][k] W[k][j] ), S=[A|X], W=[Wl;Wr].
// W = fp16 hi + fp16 lo (precomputed); S = single fp16.  D = S*Whi + S*Wlo, f32 accum.
// smem (word-indexed, k-pair-major):
//   sW{hi,lo}[col][p], p=k/2 in 0..127, row stride 132 words (copied linearly from gmem)
//   sS[node][p], p in 0..63 per 128-k chunk, row stride 68 words
// Fragments (m16n8k16.row.col, g=lane>>2, t=lane&3, p0=kstep*8, W chunk base kc*64):
//   a0=sS[m0+g][p0+t] a1=sS[m0+g+8][p0+t] a2=sS[m0+g][p0+t+4] a3=sS[m0+g+8][p0+t+4]
//   b0=sW[n0+g][kc*64+p0+t] b1=sW[n0+g][kc*64+p0+t+4]
// Warp w owns cols [16w,16w+16) (2 n-tiles), loops 8 m-tiles; acc = 8*2*4 = 64 f32.
#define WSTRIDE 132
#define SSTRIDE 68
#define SM_BIAS 0
#define SM_WHI  512
#define SM_WLO  (512 + 128 * WSTRIDE * 4)
#define SM_S    (512 + 2 * 128 * WSTRIDE * 4)
#define LAYER_SMEM (SM_S + 128 * SSTRIDE * 4)

__global__ void __launch_bounds__(256, 1)
layer_kernel(const float* __restrict__ A, const float* __restrict__ X,
             const uint4* __restrict__ whi, const uint4* __restrict__ wlo,
             const float* __restrict__ bias, float* __restrict__ out, int n) {
    extern __shared__ char smem[];
    float* sBias = (float*)(smem + SM_BIAS);
    uint32_t* sWhi = (uint32_t*)(smem + SM_WHI);
    uint32_t* sWlo = (uint32_t*)(smem + SM_WLO);
    uint32_t* sS   = (uint32_t*)(smem + SM_S);

    int tid = threadIdx.x;
    int wid = tid >> 5;
    int lane = tid & 31;
    int g = lane >> 2;
    int t = lane & 3;
    int n0 = wid * 16;

    // ---- stage W hi/lo: pure linear copy (4224 uint4 each) ----
    {
        uint4* dh = (uint4*)sWhi;
        uint4* dl = (uint4*)sWlo;
        for (int i = tid; i < 4224; i += 256) {
            dh[i] = whi[i];
            dl[i] = wlo[i];
        }
        if (tid < 128) sBias[tid] = bias[tid];
    }

    int nTiles = (n + 127) >> 7;
    for (int tile = blockIdx.x; tile < nTiles; tile += gridDim.x) {
        float acc[8][2][4];
        #pragma unroll
        for (int m = 0; m < 8; m++)
            #pragma unroll
            for (int nt = 0; nt < 2; nt++)
                #pragma unroll
                for (int q = 0; q < 4; q++) acc[m][nt][q] = 0.f;

        #pragma unroll
        for (int kc = 0; kc < 2; kc++) {
            __syncthreads();   // protects sS reuse (and sW staging on first pass)
            // stage S chunk (128 nodes x 128 k) as fp16: warp = 1 node row / pass
            {
                int q = tid & 31;          // float4 index 0..31 within row
                int nl0 = tid >> 5;        // 0..7
                const float* base = (kc == 0) ? A : X;
                #pragma unroll
                for (int pass = 0; pass < 16; pass++) {
                    int nodeLoc = pass * 8 + nl0;
                    int node = tile * 128 + nodeLoc;
                    float4 v;
                    if (node < n) v = *(const float4*)(base + (size_t)node * HID + q * 4);
                    else v = make_float4(0.f, 0.f, 0.f, 0.f);
                    __half2 h0 = __float22half2_rn(make_float2(v.x, v.y));
                    __half2 h1 = __float22half2_rn(make_float2(v.z, v.w));
                    uint32_t w0 = *(uint32_t*)&h0;
                    uint32_t w1 = *(uint32_t*)&h1;
                    int wi = nodeLoc * SSTRIDE + 2 * q;   // word index, 8B aligned
                    *(ull*)(sS + wi) = (ull)w0 | ((ull)w1 << 32);
                }
            }
            __syncthreads();

            #pragma unroll
            for (int kstep = 0; kstep < 8; kstep++) {
                int p0 = kstep * 8;
                // B fragments for 2 n-tiles, hi+lo  (+ kc*64 selects the K-chunk)
                uint32_t bhi[2][2], blo[2][2];
                #pragma unroll
                for (int nt = 0; nt < 2; nt++) {
                    int wrow = (n0 + nt * 8 + g) * WSTRIDE + kc * 64 + p0 + t;
                    bhi[nt][0] = sWhi[wrow];
                    bhi[nt][1] = sWhi[wrow + 4];
                    blo[nt][0] = sWlo[wrow];
                    blo[nt][1] = sWlo[wrow + 4];
                }
                #pragma unroll
                for (int m = 0; m < 8; m++) {
                    int r0 = (m * 16 + g) * SSTRIDE + p0 + t;
                    int r1 = r0 + 8 * SSTRIDE;
                    uint32_t a0 = sS[r0], a1 = sS[r1];
                    uint32_t a2 = sS[r0 + 4], a3 = sS[r1 + 4];
                    #pragma unroll
                    for (int nt = 0; nt < 2; nt++) {
                        MMA_F16(acc[m][nt], a0, a1, a2, a3, bhi[nt][0], bhi[nt][1]);
                        MMA_F16(acc[m][nt], a0, a1, a2, a3, blo[nt][0], blo[nt][1]);
                    }
                }
            }
        }

        // epilogue: bias + relu + store. Thread (m,nt): rows m*16+g, +8; cols n0+nt*8+2t,+1.
        #pragma unroll
        for (int m = 0; m < 8; m++) {
            #pragma unroll
            for (int nt = 0; nt < 2; nt++) {
                int col = n0 + nt * 8 + 2 * t;
                float b0 = sBias[col], b1 = sBias[col + 1];
                int node0 = tile * 128 + m * 16 + g;
                if (node0 < n) {
                    float2 o;
                    o.x = fmaxf(acc[m][nt][0] + b0, 0.f);
                    o.y = fmaxf(acc[m][nt][1] + b1, 0.f);
                    *(float2*)(out + (size_t)node0 * HID + col) = o;
                }
                int node1 = node0 + 8;
                if (node1 < n) {
                    float2 o;
                    o.x = fmaxf(acc[m][nt][2] + b0, 0.f);
                    o.y = fmaxf(acc[m][nt][3] + b1, 0.f);
                    *(float2*)(out + (size_t)node1 * HID + col) = o;
                }
            }
        }
    }
}

// ---------------- logits head: warp per node ----------------
__global__ void logits_kernel(const float* __restrict__ h, const float* __restrict__ Wout,
                              const float* __restrict__ bout, float* __restrict__ out, int n) {
    int w = (blockIdx.x * blockDim.x + threadIdx.x) >> 5;
    int lane = threadIdx.x & 31;
    if (w >= n) return;
    float4 v = ((const float4*)(h + (size_t)w * HID))[lane];
    int k = lane * 4;
    float s0 = v.x * Wout[(k + 0) * 2 + 0] + v.y * Wout[(k + 1) * 2 + 0] +
               v.z * Wout[(k + 2) * 2 + 0] + v.w * Wout[(k + 3) * 2 + 0];
    float s1 = v.x * Wout[(k + 0) * 2 + 1] + v.y * Wout[(k + 1) * 2 + 1] +
               v.z * Wout[(k + 2) * 2 + 1] + v.w * Wout[(k + 3) * 2 + 1];
    #pragma unroll
    for (int off = 16; off > 0; off >>= 1) {
        s0 += __shfl_xor_sync(0xFFFFFFFFu, s0, off);
        s1 += __shfl_xor_sync(0xFFFFFFFFu, s1, off);
    }
    if (lane == 0) {
        out[(size_t)w * 2 + 0] = s0 + bout[0];
        out[(size_t)w * 2 + 1] = s1 + bout[1];
    }
}

// ---------------- launch ----------------
extern "C" void kernel_launch(void* const* d_in, const int* in_sizes, int n_in,
                              void* d_out, int out_size) {
    const float* x    = (const float*)d_in[0];
    const int*   ei   = (const int*)d_in[1];   // int32 on device
    const float* W1l  = (const float*)d_in[2];
    const float* W1r  = (const float*)d_in[3];
    const float* b1   = (const float*)d_in[4];
    const float* W2l  = (const float*)d_in[5];
    const float* W2r  = (const float*)d_in[6];
    const float* b2   = (const float*)d_in[7];
    const float* Wout = (const float*)d_in[8];
    const float* bout = (const float*)d_in[9];
    float* dout = (float*)d_out;

    int n = in_sizes[0] / HID;
    int E = in_sizes[1] / 2;
    const int* src = ei;
    const int* dst = ei + E;

    int *p_counts, *p_off, *p_cursor, *p_esrc;
    float *p_aggr, *p_h1, *p_h2;
    uint4 *p_whi, *p_wlo;
    cudaGetSymbolAddress((void**)&p_counts, g_counts);
    cudaGetSymbolAddress((void**)&p_off,    g_off);
    cudaGetSymbolAddress((void**)&p_cursor, g_cursor);
    cudaGetSymbolAddress((void**)&p_esrc,   g_esrc);
    cudaGetSymbolAddress((void**)&p_aggr,   g_aggr);
    cudaGetSymbolAddress((void**)&p_h1,     g_h1);
    cudaGetSymbolAddress((void**)&p_h2,     g_h2);
    cudaGetSymbolAddress((void**)&p_whi,    g_whi);
    cudaGetSymbolAddress((void**)&p_wlo,    g_wlo);

    cudaFuncSetAttribute(layer_kernel, cudaFuncAttributeMaxDynamicSharedMemorySize, LAYER_SMEM);

    // tuple output: logits [n*2] then h [n*128]
    float* hOut = ((size_t)out_size >= (size_t)n * (HID + 2)) ? (dout + (size_t)n * 2) : p_h2;

    // ---- launches 1-4: CSR build + W split (layer1 is launch #6 -> ncu -s 5 captures it) ----
    hist_kernel<<<(E + 255) / 256, 256>>>(dst, p_counts, E);
    scan_kernel<<<1, 1024>>>(p_counts, p_off, p_cursor, n);
    fill_kernel<<<(E + 255) / 256, 256>>>(src, dst, p_cursor, p_esrc, E);
    wsplit_kernel<<<256, 256>>>(W1l, W1r, W2l, W2r);

    int gatherGrid = (n * 32 + 255) / 256;
    int nTiles = (n + 127) >> 7;
    int layerGrid = nTiles < 148 ? nTiles : 148;

    // ---- layer 1 ----
    gather_kernel<<<gatherGrid, 256>>>(x, p_esrc, p_off, p_aggr, n);
    layer_kernel<<<layerGrid, 256, LAYER_SMEM>>>(p_aggr, x, p_whi, p_wlo, b1, p_h1, n);

    // ---- layer 2 ----
    gather_kernel<<<gatherGrid, 256>>>(p_h1, p_esrc, p_off, p_aggr, n);
    layer_kernel<<<layerGrid, 256, LAYER_SMEM>>>(p_aggr, p_h1, p_whi + 4224, p_wlo + 4224,
                                                 b2, hOut, n);

    // ---- head ----
    logits_kernel<<<(n * 32 + 255) / 256, 256>>>(hOut, Wout, bout, dout, n);
}